// round 10
// baseline (speedup 1.0000x reference)
#include <cuda_runtime.h>
#include <cstdint>

#define BB 256
#define TT 512
#define II 64
#define HH 512
#define OO 24

#define CLUSTER_NCTAS 8
#define NBLOCKS 128
#define NTHREADS 512

#define BM 16     // batch rows per cluster
#define HC 64     // hidden cols per CTA (rank)

typedef unsigned long long u64;

// SMEM: Hs[2][16][512] double-buffered swizzled h (64KB) + Xs[16][64] (4KB)
#define HS_FLOATS (BM * HH)                   // 8192 per buffer
#define SMEM_BYTES ((2 * HS_FLOATS + BM * II) * 4)   // 69632

#define FFMA2(acc, a, w) \
    asm("fma.rn.f32x2 %0, %1, %2, %0;" : "+l"(acc) : "l"(a), "l"(w))

__device__ __forceinline__ uint32_t smem_u32(const void* p) {
    uint32_t a;
    asm("{ .reg .u64 t; cvta.to.shared.u64 t, %1; cvt.u32.u64 %0, t; }"
        : "=r"(a) : "l"(p));
    return a;
}

__global__ void __launch_bounds__(NTHREADS, 1) __cluster_dims__(CLUSTER_NCTAS, 1, 1)
rnn_persistent_kernel(const float* __restrict__ x,
                      const float* __restrict__ W_ih,
                      const float* __restrict__ W_hh,
                      const float* __restrict__ b_ih,
                      const float* __restrict__ b_hh,
                      const float* __restrict__ fc_w,
                      const float* __restrict__ fc_b,
                      float* __restrict__ out)
{
    extern __shared__ float smem[];
    float* Hs0 = smem;                        // buffer 0 (swizzled float4 pieces)
    float* Hs1 = smem + HS_FLOATS;            // buffer 1
    float* Xs  = smem + 2 * HS_FLOATS;        // [16][64]
    const u64* xq = (const u64*)Xs;

    const int tid  = threadIdx.x;
    const int lane = tid & 31;
    const int warp = tid >> 5;                // 0..15
    const int rank = blockIdx.x & (CLUSTER_NCTAS - 1);
    const int cl   = blockIdx.x >> 3;
    const int b0   = cl * BM;
    const int h0   = rank * HC;
    const int hw   = h0 + 4 * warp;           // warp's 4 h-columns
    const int k0   = lane * 16;               // lane's k-chunk
    const int i0   = lane * 2;                // lane's i-pair

    // ---- register-resident weights ----
    u64 whh[4][8];
    u64 wih[4];
    #pragma unroll
    for (int h = 0; h < 4; ++h) {
        const ulonglong2* wrow =
            (const ulonglong2*)&W_hh[(size_t)(hw + h) * HH + k0];
        #pragma unroll
        for (int j = 0; j < 4; ++j) {
            ulonglong2 v = wrow[j];
            whh[h][2 * j]     = v.x;
            whh[h][2 * j + 1] = v.y;
        }
        wih[h] = *(const u64*)&W_ih[(size_t)(hw + h) * II + i0];
    }
    const int h_idx = 2 * (lane & 1) + ((lane >> 1) & 1);   // column this lane ends with
    const float biasv = b_ih[hw + h_idx] + b_hh[hw + h_idx];

    // ---- DSMEM store targets: lane j -> rank (j>>2), column hw + h_idx ----
    // Swizzled scalar offset within a buffer: p = h>>2 (float4 piece), piece
    // stored at (p ^ ((p>>3)&3)); byte offset = piece*16 + (h&3)*4.
    const int tr   = lane >> 2;                             // target rank
    const int p_   = hw >> 2;                               // this warp's piece
    const int pp_  = p_ ^ ((p_ >> 3) & 3);
    const uint32_t loff = (uint32_t)(pp_ * 16 + h_idx * 4); // lane byte offset
    uint32_t rem0, rem1;
    {
        uint32_t a0 = smem_u32(Hs0), a1 = smem_u32(Hs1);
        asm("mapa.shared::cluster.u32 %0, %1, %2;" : "=r"(rem0) : "r"(a0), "r"(tr));
        asm("mapa.shared::cluster.u32 %0, %1, %2;" : "=r"(rem1) : "r"(a1), "r"(tr));
        rem0 += loff; rem1 += loff;
    }

    const float4* x4 = (const float4*)x;

    // ---- prefetch x_0 ----
    const int xb  = tid >> 4;
    const int xi4 = tid & 15;
    float4 xreg;
    if (tid < 256)
        xreg = x4[((size_t)(b0 + xb) * TT + 0) * 16 + xi4];

    for (int t = 0; t < TT; ++t) {
        const int rbuf = t & 1;                       // read h_{t-1} from here
        const float* HsR = rbuf ? Hs1 : Hs0;
        const uint32_t remW = rbuf ? rem0 : rem1;     // write h_t to other buffer

        // ---- commit prefetched x_t ----
        if (tid < 256)
            ((float4*)Xs)[xb * 16 + xi4] = xreg;
        __syncthreads();

        const bool rec = (t > 0);

        #pragma unroll 2
        for (int b = 0; b < BM; ++b) {
            u64 acc0 = 0ull, acc1 = 0ull, acc2 = 0ull, acc3 = 0ull;

            u64 ax = xq[b * 32 + lane];
            FFMA2(acc0, ax, wih[0]);
            FFMA2(acc1, ax, wih[1]);
            FFMA2(acc2, ax, wih[2]);
            FFMA2(acc3, ax, wih[3]);

            if (rec) {
                const ulonglong2* hrow =
                    (const ulonglong2*)(HsR + b * HH);
                #pragma unroll
                for (int j = 0; j < 4; ++j) {
                    ulonglong2 v = hrow[(lane * 4 + j) ^ ((lane >> 1) & 3)];
                    FFMA2(acc0, v.x, whh[0][2 * j]);
                    FFMA2(acc0, v.y, whh[0][2 * j + 1]);
                    FFMA2(acc1, v.x, whh[1][2 * j]);
                    FFMA2(acc1, v.y, whh[1][2 * j + 1]);
                    FFMA2(acc2, v.x, whh[2][2 * j]);
                    FFMA2(acc2, v.y, whh[2][2 * j + 1]);
                    FFMA2(acc3, v.x, whh[3][2 * j]);
                    FFMA2(acc3, v.y, whh[3][2 * j + 1]);
                }
            }

            float s0, s1, s2, s3, e;
            asm("mov.b64 {%0,%1}, %2;" : "=f"(s0), "=f"(e) : "l"(acc0)); s0 += e;
            asm("mov.b64 {%0,%1}, %2;" : "=f"(s1), "=f"(e) : "l"(acc1)); s1 += e;
            asm("mov.b64 {%0,%1}, %2;" : "=f"(s2), "=f"(e) : "l"(acc2)); s2 += e;
            asm("mov.b64 {%0,%1}, %2;" : "=f"(s3), "=f"(e) : "l"(acc3)); s3 += e;

            // 6-shfl tree: afterwards EVERY lane holds the full sum for
            // column hw + h_idx(lane&3)  (groups {l, l^4, l^8, l^16} merged)
            bool o1 = lane & 1;
            float k0_ = o1 ? s2 : s0, k1_ = o1 ? s3 : s1;
            float g0_ = o1 ? s0 : s2, g1_ = o1 ? s1 : s3;
            k0_ += __shfl_xor_sync(0xffffffffu, g0_, 1);
            k1_ += __shfl_xor_sync(0xffffffffu, g1_, 1);
            bool o2 = lane & 2;
            float k_ = o2 ? k1_ : k0_;
            float g_ = o2 ? k0_ : k1_;
            k_ += __shfl_xor_sync(0xffffffffu, g_, 2);
            k_ += __shfl_xor_sync(0xffffffffu, k_, 4);
            k_ += __shfl_xor_sync(0xffffffffu, k_, 8);
            k_ += __shfl_xor_sync(0xffffffffu, k_, 16);

            float r = fmaxf(k_ + biasv, 0.f);

            // DSMEM: lane stores its column to rank (lane>>2)'s next buffer
            asm volatile("st.shared::cluster.f32 [%0], %1;"
                         :: "r"(remW + (uint32_t)(b * (HH * 4))), "f"(r)
                         : "memory");
        }

        // ---- prefetch x_{t+1} (hides under barrier) ----
        if (tid < 256 && t + 1 < TT)
            xreg = x4[((size_t)(b0 + xb) * TT + (t + 1)) * 16 + xi4];

        // ---- cluster barrier: arrive(release) orders remote stores ----
        asm volatile("barrier.cluster.arrive.aligned;" ::: "memory");
        asm volatile("barrier.cluster.wait.aligned;"   ::: "memory");
    }

    // ---- fused FC epilogue: h_T sits in Hs0 (buffer (TT)&1 == 0) ----
    // Every CTA holds all 512 h for its 16 batch rows. Ranks split outputs.
    {
        const float4* H4 = (const float4*)Hs0;
        float4 hp[4];
        #pragma unroll
        for (int i = 0; i < 4; ++i) {
            int p = lane + 32 * i;
            hp[i] = H4[warp * 128 + (p ^ ((p >> 3) & 3))];
        }
        const int o0 = rank * (OO / CLUSTER_NCTAS);   // 3 outputs per rank
        #pragma unroll
        for (int oo = 0; oo < OO / CLUSTER_NCTAS; ++oo) {
            int o = o0 + oo;
            const float4* w4 = (const float4*)(fc_w + (size_t)o * HH);
            float s = 0.f;
            #pragma unroll
            for (int i = 0; i < 4; ++i) {
                float4 wv = __ldg(&w4[lane + 32 * i]);
                s = fmaf(hp[i].x, wv.x, s);
                s = fmaf(hp[i].y, wv.y, s);
                s = fmaf(hp[i].z, wv.z, s);
                s = fmaf(hp[i].w, wv.w, s);
            }
            #pragma unroll
            for (int d = 16; d > 0; d >>= 1)
                s += __shfl_xor_sync(0xffffffffu, s, d);
            if (lane == 0)
                out[(size_t)(b0 + warp) * OO + o] = s + fc_b[o];
        }
    }
}

extern "C" void kernel_launch(void* const* d_in, const int* in_sizes, int n_in,
                              void* d_out, int out_size)
{
    const float* x    = (const float*)d_in[0];
    const float* W_ih = (const float*)d_in[1];
    const float* W_hh = (const float*)d_in[2];
    const float* b_ih = (const float*)d_in[3];
    const float* b_hh = (const float*)d_in[4];
    const float* fc_w = (const float*)d_in[5];
    const float* fc_b = (const float*)d_in[6];
    int nb = 0;
    for (int i = 0; i < n_in; ++i) {
        const float* p = (const float*)d_in[i];
        switch (in_sizes[i]) {
            case BB * TT * II: x    = p; break;
            case HH * II:      W_ih = p; break;
            case HH * HH:      W_hh = p; break;
            case OO * HH:      fc_w = p; break;
            case OO:           fc_b = p; break;
            case HH:           if (nb++ == 0) b_ih = p; else b_hh = p; break;
            default: break;
        }
    }
    float* out = (float*)d_out;

    cudaFuncSetAttribute(rnn_persistent_kernel,
                         cudaFuncAttributeMaxDynamicSharedMemorySize, SMEM_BYTES);
    rnn_persistent_kernel<<<NBLOCKS, NTHREADS, SMEM_BYTES>>>(
        x, W_ih, W_hh, b_ih, b_hh, fc_w, fc_b, out);
}